// round 6
// baseline (speedup 1.0000x reference)
#include <cuda_runtime.h>
#include <cstdint>

#define NUM_HEADS    32
#define NUM_KV_HEADS 8
#define HEAD_DIM     128
#define WINDOW       512
#define NUM_META     4
#define BLOCK_M      64
#define TILE_N       64
#define NTHREADS     256

#define QSTRIDE (NUM_HEADS * HEAD_DIM)     // 4096
#define KSTRIDE (NUM_KV_HEADS * HEAD_DIM)  // 1024

// shared memory layout (float offsets)
#define OFF_QT 0                       // [128][64]  QT[d][m]
#define OFF_KT (OFF_QT + 128 * 64)     // [128][64]  KT[d][n]
#define OFF_V  (OFF_KT + 128 * 64)     // [64][132]  V[n][d] (padded pitch)
#define OFF_PT (OFF_V + 64 * 132)      // [64][64]   PT[n][m^swz(n)]
#define OFF_AL (OFF_PT + 64 * 64)      // alpha[64]
#define OFF_L  (OFF_AL + 64)           // l[64]
#define SMEM_FLOATS (OFF_L + 64)       // 29056 floats = 113.5 KiB

// ---- packed fp32x2 helpers ----
__device__ __forceinline__ unsigned long long pack2(float x) {
    unsigned long long r; unsigned u = __float_as_uint(x);
    asm("mov.b64 %0, {%1, %1};" : "=l"(r) : "r"(u));
    return r;
}
__device__ __forceinline__ void unpack2(unsigned long long p, float& lo, float& hi) {
    unsigned a, b;
    asm("mov.b64 {%0, %1}, %2;" : "=r"(a), "=r"(b) : "l"(p));
    lo = __uint_as_float(a); hi = __uint_as_float(b);
}
#define FFMA2(d_, a_, b_) asm("fma.rn.f32x2 %0, %1, %2, %0;" : "+l"(d_) : "l"(a_), "l"(b_))
#define FMUL2(d_, a_, b_) asm("mul.rn.f32x2 %0, %1, %2;" : "=l"(d_) : "l"(a_), "l"(b_))

__global__ __launch_bounds__(NTHREADS, 2)
void swa_attn_kernel(const float* __restrict__ Q, const float* __restrict__ K,
                     const float* __restrict__ V, float* __restrict__ O)
{
    extern __shared__ float sm[];
    float* sQT = sm + OFF_QT;
    float* sKT = sm + OFF_KT;
    float* sV  = sm + OFF_V;
    float* sPT = sm + OFF_PT;
    float* sAL = sm + OFF_AL;
    float* sL  = sm + OFF_L;

    const int h   = blockIdx.y;
    const int i0  = (gridDim.x - 1 - (int)blockIdx.x) * BLOCK_M;  // heavy blocks first
    const int kh  = h >> 2;
    const int tid = threadIdx.x;
    const int lane = tid & 31;

    // phase-A tiling: thread = (mbA, nbA); 4 m-rows (2 pairs) x 4 n-cols
    const int mbA = tid >> 4;        // 0..15
    const int nbA = tid & 15;        // 0..15
    const int m0A = mbA * 4;
    const int n0A = nbA * 4;
    // phase-B tiling: warp owns 8 m-rows (4 pairs), lane owns 4 d
    const int mB0 = (tid >> 5) * 8;
    const int dB  = lane * 4;

    const float SCALE = 0.08838834764831845f;  // 1/sqrt(128)

    // ---- build QT[d][m] (transposed). lanes span m -> conflict-free STS.
    {
        const float4* Qv = (const float4*)(Q + (size_t)i0 * QSTRIDE + h * HEAD_DIM);
        #pragma unroll
        for (int it = 0; it < 8; it++) {
            int e = tid + it * NTHREADS;       // 0..2047
            int m = e & 63, c = e >> 6;        // c: float4 column 0..31
            float4 q4 = Qv[(size_t)m * (QSTRIDE / 4) + c];
            int d = c * 4;
            sQT[(d + 0) * 64 + m] = q4.x;
            sQT[(d + 1) * 64 + m] = q4.y;
            sQT[(d + 2) * 64 + m] = q4.z;
            sQT[(d + 3) * 64 + m] = q4.w;
        }
    }

    float m_run[4], l_run[4];
    #pragma unroll
    for (int r = 0; r < 4; r++) { m_run[r] = -1e30f; l_run[r] = 0.f; }

    unsigned long long acc[4][4];   // [m-pair][d] packed (m even, m odd)
    #pragma unroll
    for (int a = 0; a < 4; a++)
        #pragma unroll
        for (int b = 0; b < 4; b++) acc[a][b] = 0ull;

    const int t_lo = (i0 > WINDOW) ? ((i0 - WINDOW) >> 6) : 0;
    const int t_hi = i0 >> 6;
    const int ntiles = (t_lo == 0) ? (t_hi + 1) : (t_hi - t_lo + 2);

    for (int tix = 0; tix < ntiles; tix++) {
        const int t  = (t_lo == 0) ? tix : ((tix == 0) ? 0 : (t_lo + tix - 1));
        const int j0 = t << 6;
        const bool meta_only = (t == 0) && (t_lo >= 1);  // window moved past meta tile

        __syncthreads();  // prev tile's readers done before restaging

        // ---- stage KT (transposed) + V. lanes span n -> conflict-free STS.
        {
            const float4* K4 = (const float4*)(K + (size_t)j0 * KSTRIDE + kh * HEAD_DIM);
            const float4* V4 = (const float4*)(V + (size_t)j0 * KSTRIDE + kh * HEAD_DIM);
            #pragma unroll
            for (int it = 0; it < 8; it++) {
                int e = tid + it * NTHREADS;
                int n = e & 63, c = e >> 6;
                size_t g = (size_t)n * (KSTRIDE / 4) + c;
                float4 k4 = K4[g];
                float4 v4 = V4[g];
                int d = c * 4;
                sKT[(d + 0) * 64 + n] = k4.x;
                sKT[(d + 1) * 64 + n] = k4.y;
                sKT[(d + 2) * 64 + n] = k4.z;
                sKT[(d + 3) * 64 + n] = k4.w;
                *(float4*)&sV[n * 132 + d] = v4;
            }
        }
        __syncthreads();

        // ---- phase A: S = Q K^T, packed over m-pairs
        unsigned long long s[2][4];
        #pragma unroll
        for (int a = 0; a < 2; a++)
            #pragma unroll
            for (int b = 0; b < 4; b++) s[a][b] = 0ull;

        {
            const float* qp = sQT + m0A;
            const float* kp = sKT + n0A;
            #pragma unroll 4
            for (int d = 0; d < 128; d++) {
                ulonglong2 qa = *(const ulonglong2*)(qp + d * 64); // (m0,m1),(m2,m3)
                float4 kv = *(const float4*)(kp + d * 64);
                unsigned long long k0 = pack2(kv.x), k1 = pack2(kv.y);
                unsigned long long k2 = pack2(kv.z), k3 = pack2(kv.w);
                FFMA2(s[0][0], qa.x, k0); FFMA2(s[0][1], qa.x, k1);
                FFMA2(s[0][2], qa.x, k2); FFMA2(s[0][3], qa.x, k3);
                FFMA2(s[1][0], qa.y, k0); FFMA2(s[1][1], qa.y, k1);
                FFMA2(s[1][2], qa.y, k2); FFMA2(s[1][3], qa.y, k3);
            }
        }

        // ---- mask + scale + online softmax (16 row-mate threads per m-row)
        float p[4][4];
        #pragma unroll
        for (int mp = 0; mp < 2; mp++)
            #pragma unroll
            for (int nj = 0; nj < 4; nj++) {
                float lo, hi; unpack2(s[mp][nj], lo, hi);
                int j   = j0 + n0A + nj;
                int ilo = i0 + m0A + 2 * mp;
                bool ok0 = (ilo     >= j) && (((ilo     - j) <= WINDOW) || (j < NUM_META));
                bool ok1 = (ilo + 1 >= j) && (((ilo + 1 - j) <= WINDOW) || (j < NUM_META));
                p[2 * mp    ][nj] = ok0 ? lo * SCALE : -1e30f;
                p[2 * mp + 1][nj] = ok1 ? hi * SCALE : -1e30f;
            }

        #pragma unroll
        for (int r = 0; r < 4; r++) {
            float mx = fmaxf(fmaxf(p[r][0], p[r][1]), fmaxf(p[r][2], p[r][3]));
            #pragma unroll
            for (int o = 8; o; o >>= 1) mx = fmaxf(mx, __shfl_xor_sync(0xffffffffu, mx, o));
            float m_new = fmaxf(m_run[r], mx);
            float al = __expf(m_run[r] - m_new);
            float ps = 0.f;
            #pragma unroll
            for (int nj = 0; nj < 4; nj++) { p[r][nj] = __expf(p[r][nj] - m_new); ps += p[r][nj]; }
            #pragma unroll
            for (int o = 8; o; o >>= 1) ps += __shfl_xor_sync(0xffffffffu, ps, o);
            l_run[r] = l_run[r] * al + ps;
            m_run[r] = m_new;
            if (nbA == 0) sAL[m0A + r] = al;
        }

        // ---- write P transposed, XOR-swizzled on m (conflict-free STS.128)
        {
            int swz = (nbA & 7) << 2;                // depends on n>>2 = nbA
            float* pt = sPT + (m0A ^ swz);
            #pragma unroll
            for (int nj = 0; nj < 4; nj++) {
                float4 v4; v4.x = p[0][nj]; v4.y = p[1][nj]; v4.z = p[2][nj]; v4.w = p[3][nj];
                *(float4*)&pt[(n0A + nj) * 64] = v4;
            }
        }
        __syncthreads();

        // ---- phase B: rescale acc by alpha, then acc += P^T V
        #pragma unroll
        for (int k = 0; k < 4; k++) {
            unsigned long long ap = *(const unsigned long long*)&sAL[mB0 + 2 * k];
            FMUL2(acc[k][0], acc[k][0], ap);
            FMUL2(acc[k][1], acc[k][1], ap);
            FMUL2(acc[k][2], acc[k][2], ap);
            FMUL2(acc[k][3], acc[k][3], ap);
        }

        const int n_end = meta_only ? NUM_META : TILE_N;
        const float* vp = sV + dB;
        #pragma unroll 2
        for (int n = 0; n < n_end; n++) {
            int swz = ((n >> 2) & 7) << 2;
            ulonglong2 pp0 = *(const ulonglong2*)&sPT[n * 64 + (mB0 ^ swz)];       // (m0,m1),(m2,m3)
            ulonglong2 pp1 = *(const ulonglong2*)&sPT[n * 64 + ((mB0 + 4) ^ swz)]; // (m4,m5),(m6,m7)
            float4 v4 = *(const float4*)(vp + n * 132);
            unsigned long long v0 = pack2(v4.x), v1 = pack2(v4.y);
            unsigned long long v2 = pack2(v4.z), v3 = pack2(v4.w);
            FFMA2(acc[0][0], pp0.x, v0); FFMA2(acc[0][1], pp0.x, v1);
            FFMA2(acc[0][2], pp0.x, v2); FFMA2(acc[0][3], pp0.x, v3);
            FFMA2(acc[1][0], pp0.y, v0); FFMA2(acc[1][1], pp0.y, v1);
            FFMA2(acc[1][2], pp0.y, v2); FFMA2(acc[1][3], pp0.y, v3);
            FFMA2(acc[2][0], pp1.x, v0); FFMA2(acc[2][1], pp1.x, v1);
            FFMA2(acc[2][2], pp1.x, v2); FFMA2(acc[2][3], pp1.x, v3);
            FFMA2(acc[3][0], pp1.y, v0); FFMA2(acc[3][1], pp1.y, v1);
            FFMA2(acc[3][2], pp1.y, v2); FFMA2(acc[3][3], pp1.y, v3);
        }
    }

    // ---- epilogue
    if (nbA == 0) {
        #pragma unroll
        for (int r = 0; r < 4; r++) sL[m0A + r] = l_run[r];
    }
    __syncthreads();

    #pragma unroll
    for (int k = 0; k < 4; k++) {
        float il0 = 1.0f / sL[mB0 + 2 * k];
        float il1 = 1.0f / sL[mB0 + 2 * k + 1];
        float4 o0, o1; float lo, hi;
        unpack2(acc[k][0], lo, hi); o0.x = lo * il0; o1.x = hi * il1;
        unpack2(acc[k][1], lo, hi); o0.y = lo * il0; o1.y = hi * il1;
        unpack2(acc[k][2], lo, hi); o0.z = lo * il0; o1.z = hi * il1;
        unpack2(acc[k][3], lo, hi); o0.w = lo * il0; o1.w = hi * il1;
        size_t row = (size_t)(i0 + mB0 + 2 * k) * QSTRIDE + h * HEAD_DIM + dB;
        *(float4*)(O + row)           = o0;
        *(float4*)(O + row + QSTRIDE) = o1;
    }
}

extern "C" void kernel_launch(void* const* d_in, const int* in_sizes, int n_in,
                              void* d_out, int out_size)
{
    const float* Q = (const float*)d_in[0];
    const float* K = (const float*)d_in[1];
    const float* V = (const float*)d_in[2];
    float* O = (float*)d_out;

    const int S = in_sizes[0] / QSTRIDE;   // 2048

    cudaFuncSetAttribute(swa_attn_kernel,
                         cudaFuncAttributeMaxDynamicSharedMemorySize,
                         SMEM_FLOATS * 4);

    dim3 grid(S / BLOCK_M, NUM_HEADS);
    swa_attn_kernel<<<grid, NTHREADS, SMEM_FLOATS * 4>>>(Q, K, V, O);
}

// round 7
// speedup vs baseline: 1.0265x; 1.0265x over previous
#include <cuda_runtime.h>
#include <cstdint>

#define NUM_HEADS    32
#define NUM_KV_HEADS 8
#define HEAD_DIM     128
#define WINDOW       512
#define NUM_META     4
#define BLOCK_M      64
#define TILE_N       64
#define NTHREADS     256

#define QSTRIDE (NUM_HEADS * HEAD_DIM)     // 4096
#define KSTRIDE (NUM_KV_HEADS * HEAD_DIM)  // 1024

// shared memory layout (float offsets)
#define OFF_QT 0                       // [128][64]  QT[d][m]
#define OFF_KT (OFF_QT + 128 * 64)     // [128][64]  KT[d][n]
#define OFF_V  (OFF_KT + 128 * 64)     // [64][128]  V[n][d4^(n&7)] xor-swizzled float4
#define OFF_PT (OFF_V + 64 * 128)      // [64][64]   PT[n][m^swz(n)]
#define OFF_AL (OFF_PT + 64 * 64)      // alpha[64]
#define OFF_L  (OFF_AL + 64)           // l[64]
#define SMEM_FLOATS (OFF_L + 64)       // 28800 floats = 115200 B -> 2 blocks/SM

// ---- packed fp32x2 helpers ----
__device__ __forceinline__ unsigned long long pack2(float x) {
    unsigned long long r; unsigned u = __float_as_uint(x);
    asm("mov.b64 %0, {%1, %1};" : "=l"(r) : "r"(u));
    return r;
}
__device__ __forceinline__ void unpack2(unsigned long long p, float& lo, float& hi) {
    unsigned a, b;
    asm("mov.b64 {%0, %1}, %2;" : "=r"(a), "=r"(b) : "l"(p));
    lo = __uint_as_float(a); hi = __uint_as_float(b);
}
#define FFMA2(d_, a_, b_) asm("fma.rn.f32x2 %0, %1, %2, %0;" : "+l"(d_) : "l"(a_), "l"(b_))
#define FMUL2(d_, a_, b_) asm("mul.rn.f32x2 %0, %1, %2;" : "=l"(d_) : "l"(a_), "l"(b_))

__global__ __launch_bounds__(NTHREADS, 2)
void swa_attn_kernel(const float* __restrict__ Q, const float* __restrict__ K,
                     const float* __restrict__ V, float* __restrict__ O)
{
    extern __shared__ float sm[];
    float*  sQT = sm + OFF_QT;
    float*  sKT = sm + OFF_KT;
    float4* sV4 = (float4*)(sm + OFF_V);
    float*  sPT = sm + OFF_PT;
    float*  sAL = sm + OFF_AL;
    float*  sL  = sm + OFF_L;

    const int h   = blockIdx.y;
    const int i0  = (gridDim.x - 1 - (int)blockIdx.x) * BLOCK_M;  // heavy blocks first
    const int kh  = h >> 2;
    const int tid = threadIdx.x;

    // phase-A tiling: thread = (mbA, nbA); 4 m-rows (2 pairs) x 4 n-cols
    const int mbA = tid >> 4;        // 0..15
    const int nbA = tid & 15;        // 0..15
    const int m0A = mbA * 4;
    const int n0A = nbA * 4;
    // phase-B tiling: warp owns 8 m-rows (4 pairs), lane owns 4 d
    const int lane = tid & 31;
    const int mB0 = (tid >> 5) * 8;
    const int dB4 = lane;            // float4 column 0..31

    const float SCALE = 0.08838834764831845f;  // 1/sqrt(128)

    // ---- build QT[d][m] (transposed). lanes span m -> conflict-free STS.
    {
        const float4* Qv = (const float4*)(Q + (size_t)i0 * QSTRIDE + h * HEAD_DIM);
        #pragma unroll
        for (int it = 0; it < 8; it++) {
            int e = tid + it * NTHREADS;       // 0..2047
            int m = e & 63, c = e >> 6;        // c: float4 column 0..31
            float4 q4 = Qv[(size_t)m * (QSTRIDE / 4) + c];
            int d = c * 4;
            sQT[(d + 0) * 64 + m] = q4.x;
            sQT[(d + 1) * 64 + m] = q4.y;
            sQT[(d + 2) * 64 + m] = q4.z;
            sQT[(d + 3) * 64 + m] = q4.w;
        }
    }

    float m_run[4], l_run[4];
    #pragma unroll
    for (int r = 0; r < 4; r++) { m_run[r] = -1e30f; l_run[r] = 0.f; }

    unsigned long long acc[4][4];   // [m-pair][d] packed (m even, m odd)
    #pragma unroll
    for (int a = 0; a < 4; a++)
        #pragma unroll
        for (int b = 0; b < 4; b++) acc[a][b] = 0ull;

    const int t_lo = (i0 > WINDOW) ? ((i0 - WINDOW) >> 6) : 0;
    const int t_hi = i0 >> 6;
    const int ntiles = (t_lo == 0) ? (t_hi + 1) : (t_hi - t_lo + 2);

    for (int tix = 0; tix < ntiles; tix++) {
        const int t  = (t_lo == 0) ? tix : ((tix == 0) ? 0 : (t_lo + tix - 1));
        const int j0 = t << 6;
        const bool meta_only = (t == 0) && (t_lo >= 1);  // window moved past meta tile

        __syncthreads();  // prev tile's readers done before restaging

        // ---- stage KT (transposed) + V (xor-swizzled). lanes span n -> conflict-free.
        {
            const float4* K4 = (const float4*)(K + (size_t)j0 * KSTRIDE + kh * HEAD_DIM);
            const float4* V4 = (const float4*)(V + (size_t)j0 * KSTRIDE + kh * HEAD_DIM);
            #pragma unroll
            for (int it = 0; it < 8; it++) {
                int e = tid + it * NTHREADS;
                int n = e & 63, c = e >> 6;
                size_t g = (size_t)n * (KSTRIDE / 4) + c;
                float4 k4 = K4[g];
                float4 v4 = V4[g];
                int d = c * 4;
                sKT[(d + 0) * 64 + n] = k4.x;
                sKT[(d + 1) * 64 + n] = k4.y;
                sKT[(d + 2) * 64 + n] = k4.z;
                sKT[(d + 3) * 64 + n] = k4.w;
                sV4[n * 32 + (c ^ (n & 7))] = v4;
            }
        }
        __syncthreads();

        // ---- phase A: S = Q K^T, packed over m-pairs
        unsigned long long s[2][4];
        #pragma unroll
        for (int a = 0; a < 2; a++)
            #pragma unroll
            for (int b = 0; b < 4; b++) s[a][b] = 0ull;

        {
            const float* qp = sQT + m0A;
            const float* kp = sKT + n0A;
            #pragma unroll 4
            for (int d = 0; d < 128; d++) {
                ulonglong2 qa = *(const ulonglong2*)(qp + d * 64); // (m0,m1),(m2,m3)
                float4 kv = *(const float4*)(kp + d * 64);
                unsigned long long k0 = pack2(kv.x), k1 = pack2(kv.y);
                unsigned long long k2 = pack2(kv.z), k3 = pack2(kv.w);
                FFMA2(s[0][0], qa.x, k0); FFMA2(s[0][1], qa.x, k1);
                FFMA2(s[0][2], qa.x, k2); FFMA2(s[0][3], qa.x, k3);
                FFMA2(s[1][0], qa.y, k0); FFMA2(s[1][1], qa.y, k1);
                FFMA2(s[1][2], qa.y, k2); FFMA2(s[1][3], qa.y, k3);
            }
        }

        // ---- mask + scale + online softmax (16 row-mate threads per m-row)
        float p[4][4];
        #pragma unroll
        for (int mp = 0; mp < 2; mp++)
            #pragma unroll
            for (int nj = 0; nj < 4; nj++) {
                float lo, hi; unpack2(s[mp][nj], lo, hi);
                int j   = j0 + n0A + nj;
                int ilo = i0 + m0A + 2 * mp;
                bool ok0 = (ilo     >= j) && (((ilo     - j) <= WINDOW) || (j < NUM_META));
                bool ok1 = (ilo + 1 >= j) && (((ilo + 1 - j) <= WINDOW) || (j < NUM_META));
                p[2 * mp    ][nj] = ok0 ? lo * SCALE : -1e30f;
                p[2 * mp + 1][nj] = ok1 ? hi * SCALE : -1e30f;
            }

        #pragma unroll
        for (int r = 0; r < 4; r++) {
            float mx = fmaxf(fmaxf(p[r][0], p[r][1]), fmaxf(p[r][2], p[r][3]));
            #pragma unroll
            for (int o = 8; o; o >>= 1) mx = fmaxf(mx, __shfl_xor_sync(0xffffffffu, mx, o));
            float m_new = fmaxf(m_run[r], mx);
            float al = __expf(m_run[r] - m_new);
            float ps = 0.f;
            #pragma unroll
            for (int nj = 0; nj < 4; nj++) { p[r][nj] = __expf(p[r][nj] - m_new); ps += p[r][nj]; }
            #pragma unroll
            for (int o = 8; o; o >>= 1) ps += __shfl_xor_sync(0xffffffffu, ps, o);
            l_run[r] = l_run[r] * al + ps;
            m_run[r] = m_new;
            if (nbA == 0) sAL[m0A + r] = al;
        }

        // ---- write P transposed, XOR-swizzled on m (conflict-free STS.128)
        {
            int swz = (nbA & 7) << 2;                // depends on n>>2 = nbA
            float* pt = sPT + (m0A ^ swz);
            #pragma unroll
            for (int nj = 0; nj < 4; nj++) {
                float4 v4; v4.x = p[0][nj]; v4.y = p[1][nj]; v4.z = p[2][nj]; v4.w = p[3][nj];
                *(float4*)&pt[(n0A + nj) * 64] = v4;
            }
        }
        __syncthreads();

        // ---- phase B: rescale acc by alpha, then acc += P^T V
        #pragma unroll
        for (int k = 0; k < 4; k++) {
            unsigned long long ap = *(const unsigned long long*)&sAL[mB0 + 2 * k];
            FMUL2(acc[k][0], acc[k][0], ap);
            FMUL2(acc[k][1], acc[k][1], ap);
            FMUL2(acc[k][2], acc[k][2], ap);
            FMUL2(acc[k][3], acc[k][3], ap);
        }

        const int n_end = meta_only ? NUM_META : TILE_N;
        #pragma unroll 2
        for (int n = 0; n < n_end; n++) {
            int swz = ((n >> 2) & 7) << 2;
            ulonglong2 pp0 = *(const ulonglong2*)&sPT[n * 64 + (mB0 ^ swz)];       // (m0,m1),(m2,m3)
            ulonglong2 pp1 = *(const ulonglong2*)&sPT[n * 64 + ((mB0 + 4) ^ swz)]; // (m4,m5),(m6,m7)
            float4 v4 = sV4[n * 32 + (dB4 ^ (n & 7))];
            unsigned long long v0 = pack2(v4.x), v1 = pack2(v4.y);
            unsigned long long v2 = pack2(v4.z), v3 = pack2(v4.w);
            FFMA2(acc[0][0], pp0.x, v0); FFMA2(acc[0][1], pp0.x, v1);
            FFMA2(acc[0][2], pp0.x, v2); FFMA2(acc[0][3], pp0.x, v3);
            FFMA2(acc[1][0], pp0.y, v0); FFMA2(acc[1][1], pp0.y, v1);
            FFMA2(acc[1][2], pp0.y, v2); FFMA2(acc[1][3], pp0.y, v3);
            FFMA2(acc[2][0], pp1.x, v0); FFMA2(acc[2][1], pp1.x, v1);
            FFMA2(acc[2][2], pp1.x, v2); FFMA2(acc[2][3], pp1.x, v3);
            FFMA2(acc[3][0], pp1.y, v0); FFMA2(acc[3][1], pp1.y, v1);
            FFMA2(acc[3][2], pp1.y, v2); FFMA2(acc[3][3], pp1.y, v3);
        }
    }

    // ---- epilogue
    if (nbA == 0) {
        #pragma unroll
        for (int r = 0; r < 4; r++) sL[m0A + r] = l_run[r];
    }
    __syncthreads();

    #pragma unroll
    for (int k = 0; k < 4; k++) {
        float il0 = 1.0f / sL[mB0 + 2 * k];
        float il1 = 1.0f / sL[mB0 + 2 * k + 1];
        float4 o0, o1; float lo, hi;
        unpack2(acc[k][0], lo, hi); o0.x = lo * il0; o1.x = hi * il1;
        unpack2(acc[k][1], lo, hi); o0.y = lo * il0; o1.y = hi * il1;
        unpack2(acc[k][2], lo, hi); o0.z = lo * il0; o1.z = hi * il1;
        unpack2(acc[k][3], lo, hi); o0.w = lo * il0; o1.w = hi * il1;
        size_t row = (size_t)(i0 + mB0 + 2 * k) * QSTRIDE + h * HEAD_DIM + dB4 * 4;
        *(float4*)(O + row)           = o0;
        *(float4*)(O + row + QSTRIDE) = o1;
    }
}

extern "C" void kernel_launch(void* const* d_in, const int* in_sizes, int n_in,
                              void* d_out, int out_size)
{
    const float* Q = (const float*)d_in[0];
    const float* K = (const float*)d_in[1];
    const float* V = (const float*)d_in[2];
    float* O = (float*)d_out;

    const int S = in_sizes[0] / QSTRIDE;   // 2048

    cudaFuncSetAttribute(swa_attn_kernel,
                         cudaFuncAttributeMaxDynamicSharedMemorySize,
                         SMEM_FLOATS * 4);

    dim3 grid(S / BLOCK_M, NUM_HEADS);
    swa_attn_kernel<<<grid, NTHREADS, SMEM_FLOATS * 4>>>(Q, K, V, O);
}

// round 9
// speedup vs baseline: 1.5143x; 1.4751x over previous
#include <cuda_runtime.h>
#include <cuda_bf16.h>
#include <cstdint>

#define WINDOW 512
#define NMETA  4
#define BM     128
#define NTH    256
#define QSTR   4096
#define KSTR   1024
#define SCALE  0.08838834764831845f

// smem byte offsets: bf16 tiles, 256B row pitch, XOR-swizzled 16B groups
#define SM_QH 0
#define SM_QL 32768
#define SM_KH 65536
#define SM_KL 81920
#define SM_VH 98304
#define SM_VL 114688
#define SMEM_BYTES 131072

__device__ __forceinline__ uint32_t s2u(const void* p){
    uint32_t a;
    asm("{ .reg .u64 t; cvta.to.shared.u64 t, %1; cvt.u32.u64 %0, t; }":"=r"(a):"l"(p));
    return a;
}
// byte offset of 16B group holding (row, col) in a [rows][128] bf16 tile, pitch 256B
__device__ __forceinline__ uint32_t swoff(int row, int col){
    return (uint32_t)(row * 256 + (((col >> 3) ^ (row & 7)) << 4));
}
__device__ __forceinline__ void split2(float a, float b, uint32_t& hp, uint32_t& lp){
    __nv_bfloat16 ah = __float2bfloat16(a), bh = __float2bfloat16(b);
    __nv_bfloat16 al = __float2bfloat16(a - __bfloat162float(ah));
    __nv_bfloat16 bl = __float2bfloat16(b - __bfloat162float(bh));
    hp = (uint32_t)__bfloat16_as_ushort(ah) | ((uint32_t)__bfloat16_as_ushort(bh) << 16);
    lp = (uint32_t)__bfloat16_as_ushort(al) | ((uint32_t)__bfloat16_as_ushort(bl) << 16);
}
__device__ __forceinline__ void ldsm4(uint32_t a, uint32_t r[4]){
    asm volatile("ldmatrix.sync.aligned.m8n8.x4.shared.b16 {%0,%1,%2,%3},[%4];"
        : "=r"(r[0]), "=r"(r[1]), "=r"(r[2]), "=r"(r[3]) : "r"(a));
}
__device__ __forceinline__ void ldsm2(uint32_t a, uint32_t r[2]){
    asm volatile("ldmatrix.sync.aligned.m8n8.x2.shared.b16 {%0,%1},[%2];"
        : "=r"(r[0]), "=r"(r[1]) : "r"(a));
}
__device__ __forceinline__ void ldsm2t(uint32_t a, uint32_t r[2]){
    asm volatile("ldmatrix.sync.aligned.m8n8.x2.trans.shared.b16 {%0,%1},[%2];"
        : "=r"(r[0]), "=r"(r[1]) : "r"(a));
}
__device__ __forceinline__ void mma16816(float d[4], const uint32_t a[4], const uint32_t b[2]){
    asm volatile("mma.sync.aligned.m16n8k16.row.col.f32.bf16.bf16.f32 "
        "{%0,%1,%2,%3},{%4,%5,%6,%7},{%8,%9},{%0,%1,%2,%3};"
        : "+f"(d[0]), "+f"(d[1]), "+f"(d[2]), "+f"(d[3])
        : "r"(a[0]), "r"(a[1]), "r"(a[2]), "r"(a[3]), "r"(b[0]), "r"(b[1]));
}

__global__ __launch_bounds__(NTH, 1)
void swa_mma_kernel(const float* __restrict__ Q, const float* __restrict__ K,
                    const float* __restrict__ V, float* __restrict__ O)
{
    extern __shared__ char smp[];
    const uint32_t sb = s2u(smp);

    const int tid = threadIdx.x, wid = tid >> 5, lane = tid & 31;
    const int h = blockIdx.y, kh = h >> 2;
    const int i0 = ((int)gridDim.x - 1 - (int)blockIdx.x) * BM;  // heavy blocks first

    const int m0 = wid * 16;
    const int r  = lane >> 2;
    const int c2 = (lane & 3) * 2;

    // ---- stage Q -> bf16 hi/lo (swizzled [m][d], pitch 256B)
    {
        const float4* Q4 = (const float4*)(Q + (size_t)i0 * QSTR + h * 128);
        #pragma unroll
        for (int it = 0; it < 16; it++) {
            int e = tid + it * NTH, m = e >> 5, c4 = e & 31, d = c4 * 4;
            float4 q = Q4[(size_t)m * (QSTR / 4) + c4];
            uint32_t h01, l01, h23, l23;
            split2(q.x, q.y, h01, l01); split2(q.z, q.w, h23, l23);
            uint32_t off = swoff(m, d) + (uint32_t)((d & 7) * 2);
            *(uint2*)(smp + SM_QH + off) = make_uint2(h01, h23);
            *(uint2*)(smp + SM_QL + off) = make_uint2(l01, l23);
        }
    }

    float l0 = 0.f, l1 = 0.f;
    float o[16][4];
    #pragma unroll
    for (int dt = 0; dt < 16; dt++)
        #pragma unroll
        for (int e = 0; e < 4; e++) o[dt][e] = 0.f;

    const int t_lo = (i0 > WINDOW) ? ((i0 - WINDOW) >> 6) : 0;
    const int t_hi = (i0 + BM - 1) >> 6;
    const int ntiles = (t_lo == 0) ? (t_hi + 1) : (t_hi - t_lo + 2);

    for (int tix = 0; tix < ntiles; tix++) {
        const int t  = (t_lo == 0) ? tix : ((tix == 0) ? 0 : (t_lo + tix - 1));
        const int j0 = t << 6;
        const bool meta_only = (t == 0) && (t_lo >= 1);

        if (tix > 0) __syncthreads();   // prev tile's readers done

        // ---- stage K,V tile -> bf16 hi/lo (swizzled [n][d])
        {
            const float4* K4 = (const float4*)(K + (size_t)j0 * KSTR + kh * 128);
            const float4* V4 = (const float4*)(V + (size_t)j0 * KSTR + kh * 128);
            const int its = meta_only ? 2 : 8;
            for (int it = 0; it < its; it++) {
                int e = tid + it * NTH, n = e >> 5, c4 = e & 31, d = c4 * 4;
                size_t g = (size_t)n * (KSTR / 4) + c4;
                float4 k = K4[g];
                float4 v = V4[g];
                uint32_t h01, l01, h23, l23;
                uint32_t off = swoff(n, d) + (uint32_t)((d & 7) * 2);
                split2(k.x, k.y, h01, l01); split2(k.z, k.w, h23, l23);
                *(uint2*)(smp + SM_KH + off) = make_uint2(h01, h23);
                *(uint2*)(smp + SM_KL + off) = make_uint2(l01, l23);
                split2(v.x, v.y, h01, l01); split2(v.z, v.w, h23, l23);
                *(uint2*)(smp + SM_VH + off) = make_uint2(h01, h23);
                *(uint2*)(smp + SM_VL + off) = make_uint2(l01, l23);
            }
        }
        __syncthreads();

        // ---- QK^T: S = Qh*Kh + Ql*Kh + Qh*Kl
        float s[8][4];
        #pragma unroll
        for (int nt = 0; nt < 8; nt++)
            #pragma unroll
            for (int e = 0; e < 4; e++) s[nt][e] = 0.f;

        const int ntc = meta_only ? 2 : 8;
        #pragma unroll
        for (int ks = 0; ks < 8; ks++) {
            const int d0 = ks * 16;
            const int ar = m0 + (lane & 7) + (lane & 8);
            const int ac = d0 + ((lane & 16) >> 1);
            uint32_t ah[4], al[4];
            ldsm4(sb + SM_QH + swoff(ar, ac), ah);
            ldsm4(sb + SM_QL + swoff(ar, ac), al);
            for (int nt = 0; nt < ntc; nt++) {
                const int br = nt * 8 + (lane & 7);
                const int bc = d0 + (lane & 8);
                uint32_t bh[2], bl[2];
                ldsm2(sb + SM_KH + swoff(br, bc), bh);
                ldsm2(sb + SM_KL + swoff(br, bc), bl);
                mma16816(s[nt], ah, bh);
                mma16816(s[nt], al, bh);
                mma16816(s[nt], ah, bl);
            }
        }

        // ---- mask + static-max softmax: p = exp(s*scale)
        {
            const int i_r0 = i0 + m0 + r, i_r1 = i_r0 + 8;
            float rs0 = 0.f, rs1 = 0.f;
            for (int nt = 0; nt < ntc; nt++) {
                const int jb = j0 + nt * 8 + c2;
                bool ok0 = (i_r0 >= jb)     && (((i_r0 - jb)     <= WINDOW) || (jb     < NMETA));
                bool ok1 = (i_r0 >= jb + 1) && (((i_r0 - jb - 1) <= WINDOW) || (jb + 1 < NMETA));
                bool ok2 = (i_r1 >= jb)     && (((i_r1 - jb)     <= WINDOW) || (jb     < NMETA));
                bool ok3 = (i_r1 >= jb + 1) && (((i_r1 - jb - 1) <= WINDOW) || (jb + 1 < NMETA));
                float p0 = ok0 ? __expf(s[nt][0] * SCALE) : 0.f;
                float p1 = ok1 ? __expf(s[nt][1] * SCALE) : 0.f;
                float p2 = ok2 ? __expf(s[nt][2] * SCALE) : 0.f;
                float p3 = ok3 ? __expf(s[nt][3] * SCALE) : 0.f;
                s[nt][0] = p0; s[nt][1] = p1; s[nt][2] = p2; s[nt][3] = p3;
                rs0 += p0 + p1; rs1 += p2 + p3;
            }
            rs0 += __shfl_xor_sync(0xffffffffu, rs0, 1);
            rs0 += __shfl_xor_sync(0xffffffffu, rs0, 2);
            rs1 += __shfl_xor_sync(0xffffffffu, rs1, 1);
            rs1 += __shfl_xor_sync(0xffffffffu, rs1, 2);
            l0 += rs0; l1 += rs1;
        }

        // ---- PV: O += Ph*Vh + Pl*Vh + Ph*Vl  (P converted in registers)
        const int kc = meta_only ? 1 : 4;
        for (int kk = 0; kk < kc; kk++) {
            uint32_t pah[4], pal[4];
            split2(s[2 * kk][0],     s[2 * kk][1],     pah[0], pal[0]);
            split2(s[2 * kk][2],     s[2 * kk][3],     pah[1], pal[1]);
            split2(s[2 * kk + 1][0], s[2 * kk + 1][1], pah[2], pal[2]);
            split2(s[2 * kk + 1][2], s[2 * kk + 1][3], pah[3], pal[3]);
            const int vr = kk * 16 + (lane & 15);
            #pragma unroll
            for (int dt = 0; dt < 16; dt++) {
                uint32_t bh[2], bl[2];
                ldsm2t(sb + SM_VH + swoff(vr, dt * 8), bh);
                ldsm2t(sb + SM_VL + swoff(vr, dt * 8), bl);
                mma16816(o[dt], pah, bh);
                mma16816(o[dt], pal, bh);
                mma16816(o[dt], pah, bl);
            }
        }
    }

    // ---- epilogue: normalize, store
    const float inv0 = 1.0f / l0, inv1 = 1.0f / l1;
    float* ob = O + (size_t)(i0 + m0 + r) * QSTR + h * 128 + c2;
    #pragma unroll
    for (int dt = 0; dt < 16; dt++) {
        float2 s0, s1;
        s0.x = o[dt][0] * inv0; s0.y = o[dt][1] * inv0;
        s1.x = o[dt][2] * inv1; s1.y = o[dt][3] * inv1;
        *(float2*)(ob + dt * 8)               = s0;
        *(float2*)(ob + dt * 8 + 8 * QSTR)    = s1;
    }
}

extern "C" void kernel_launch(void* const* d_in, const int* in_sizes, int n_in,
                              void* d_out, int out_size)
{
    const float* Q = (const float*)d_in[0];
    const float* K = (const float*)d_in[1];
    const float* V = (const float*)d_in[2];
    float* O = (float*)d_out;

    const int S = in_sizes[0] / QSTR;   // 2048

    cudaFuncSetAttribute(swa_mma_kernel,
                         cudaFuncAttributeMaxDynamicSharedMemorySize, SMEM_BYTES);

    dim3 grid(S / BM, 32);
    swa_mma_kernel<<<grid, NTH, SMEM_BYTES>>>(Q, K, V, O);
}

// round 10
// speedup vs baseline: 2.0540x; 1.3564x over previous
#include <cuda_runtime.h>
#include <cuda_bf16.h>
#include <cstdint>

#define WINDOW 512
#define NMETA  4
#define BM     64
#define NTH    128
#define QSTR   4096
#define KSTR   1024
#define SCALE  0.08838834764831845f

// smem: bf16 tiles, 256B row pitch, XOR-swizzled 16B groups
#define SM_QH 0
#define SM_QL 16384
#define SM_KH 32768
#define SM_KL 49152
#define SM_VH 65536
#define SM_VL 81920
#define SMEM_BYTES 98304

// pre-converted K/V scratch: [8 kv-heads][2048 rows][256 B], smem-identical layout
__device__ __align__(16) char g_KH[8 * 2048 * 256];
__device__ __align__(16) char g_KL[8 * 2048 * 256];
__device__ __align__(16) char g_VH[8 * 2048 * 256];
__device__ __align__(16) char g_VL[8 * 2048 * 256];

__device__ __forceinline__ uint32_t s2u(const void* p){
    uint32_t a;
    asm("{ .reg .u64 t; cvta.to.shared.u64 t, %1; cvt.u32.u64 %0, t; }":"=r"(a):"l"(p));
    return a;
}
__device__ __forceinline__ uint32_t swoff(int row, int col){
    return (uint32_t)(row * 256 + (((col >> 3) ^ (row & 7)) << 4));
}
__device__ __forceinline__ void split2(float a, float b, uint32_t& hp, uint32_t& lp){
    __nv_bfloat16 ah = __float2bfloat16(a), bh = __float2bfloat16(b);
    __nv_bfloat16 al = __float2bfloat16(a - __bfloat162float(ah));
    __nv_bfloat16 bl = __float2bfloat16(b - __bfloat162float(bh));
    hp = (uint32_t)__bfloat16_as_ushort(ah) | ((uint32_t)__bfloat16_as_ushort(bh) << 16);
    lp = (uint32_t)__bfloat16_as_ushort(al) | ((uint32_t)__bfloat16_as_ushort(bl) << 16);
}
__device__ __forceinline__ void ldsm4(uint32_t a, uint32_t r[4]){
    asm volatile("ldmatrix.sync.aligned.m8n8.x4.shared.b16 {%0,%1,%2,%3},[%4];"
        : "=r"(r[0]), "=r"(r[1]), "=r"(r[2]), "=r"(r[3]) : "r"(a));
}
__device__ __forceinline__ void ldsm2(uint32_t a, uint32_t r[2]){
    asm volatile("ldmatrix.sync.aligned.m8n8.x2.shared.b16 {%0,%1},[%2];"
        : "=r"(r[0]), "=r"(r[1]) : "r"(a));
}
__device__ __forceinline__ void ldsm2t(uint32_t a, uint32_t r[2]){
    asm volatile("ldmatrix.sync.aligned.m8n8.x2.trans.shared.b16 {%0,%1},[%2];"
        : "=r"(r[0]), "=r"(r[1]) : "r"(a));
}
__device__ __forceinline__ void mma16816(float d[4], const uint32_t a[4], const uint32_t b[2]){
    asm volatile("mma.sync.aligned.m16n8k16.row.col.f32.bf16.bf16.f32 "
        "{%0,%1,%2,%3},{%4,%5,%6,%7},{%8,%9},{%0,%1,%2,%3};"
        : "+f"(d[0]), "+f"(d[1]), "+f"(d[2]), "+f"(d[3])
        : "r"(a[0]), "r"(a[1]), "r"(a[2]), "r"(a[3]), "r"(b[0]), "r"(b[1]));
}
#define CPA(dst, src) asm volatile("cp.async.cg.shared.global [%0],[%1],16;"::"r"(dst),"l"(src):"memory")
#define CPC() asm volatile("cp.async.commit_group;":::"memory")
#define CPW() asm volatile("cp.async.wait_group 0;":::"memory")

// ---- prepass: K/V fp32 -> bf16 hi/lo scratch in swizzled layout
__global__ __launch_bounds__(256)
void prep_kv(const float* __restrict__ K, const float* __restrict__ V)
{
    int idx = blockIdx.x * 256 + threadIdx.x;   // 0 .. 8*2048*64-1
    int c2 = idx & 63;                          // column pair index (c = 2*c2)
    int n  = (idx >> 6) & 2047;
    int kh = idx >> 17;
    int c  = c2 * 2;
    const float2 k2 = *(const float2*)(K + (size_t)n * KSTR + kh * 128 + c);
    const float2 v2 = *(const float2*)(V + (size_t)n * KSTR + kh * 128 + c);
    size_t off = ((size_t)kh * 2048 + n) * 256
               + (uint32_t)((((c >> 3) ^ (n & 7)) << 4) + (c & 7) * 2);
    uint32_t hp, lp;
    split2(k2.x, k2.y, hp, lp);
    *(uint32_t*)(g_KH + off) = hp; *(uint32_t*)(g_KL + off) = lp;
    split2(v2.x, v2.y, hp, lp);
    *(uint32_t*)(g_VH + off) = hp; *(uint32_t*)(g_VL + off) = lp;
}

__global__ __launch_bounds__(NTH, 2)
void swa_mma_kernel(const float* __restrict__ Q, float* __restrict__ O)
{
    extern __shared__ char smp[];
    const uint32_t sb = s2u(smp);

    const int tid = threadIdx.x, wid = tid >> 5, lane = tid & 31;
    const int h = blockIdx.y, kh = h >> 2;
    const int i0 = ((int)gridDim.x - 1 - (int)blockIdx.x) * BM;  // heavy blocks first

    const int m0 = wid * 16;
    const int r  = lane >> 2;
    const int c2 = (lane & 3) * 2;

    // ---- stage Q -> bf16 hi/lo (swizzled [m][d]); once per CTA
    {
        const float4* Q4 = (const float4*)(Q + (size_t)i0 * QSTR + h * 128);
        #pragma unroll
        for (int it = 0; it < 16; it++) {
            int e = tid + it * NTH, m = e >> 5, c4 = e & 31, d = c4 * 4;
            float4 q = Q4[(size_t)m * (QSTR / 4) + c4];
            uint32_t h01, l01, h23, l23;
            split2(q.x, q.y, h01, l01); split2(q.z, q.w, h23, l23);
            uint32_t off = swoff(m, d) + (uint32_t)((d & 7) * 2);
            *(uint2*)(smp + SM_QH + off) = make_uint2(h01, h23);
            *(uint2*)(smp + SM_QL + off) = make_uint2(l01, l23);
        }
    }

    float l0 = 0.f, l1 = 0.f;
    float o[16][4];
    #pragma unroll
    for (int dt = 0; dt < 16; dt++)
        #pragma unroll
        for (int e = 0; e < 4; e++) o[dt][e] = 0.f;

    const int t_lo = (i0 > WINDOW) ? ((i0 - WINDOW) >> 6) : 0;
    const int t_hi = i0 >> 6;
    const int ntiles = (t_lo == 0) ? (t_hi + 1) : (t_hi - t_lo + 2);

    for (int tix = 0; tix < ntiles; tix++) {
        const int t  = (t_lo == 0) ? tix : ((tix == 0) ? 0 : (t_lo + tix - 1));
        const int j0 = t << 6;
        const bool meta_only = (t == 0) && (t_lo >= 1);

        if (tix > 0) __syncthreads();   // prev tile's smem readers done

        // ---- stage K,V tile: plain 16B async copies from pre-swizzled scratch
        {
            const size_t base = ((size_t)kh * 2048 + j0) * 256;
            const int ng = meta_only ? 256 : 1024;   // 16 rows vs 64 rows
            for (int g = tid; g < ng; g += NTH) {
                uint32_t go = (uint32_t)g * 16;
                CPA(sb + SM_KH + go, g_KH + base + go);
                CPA(sb + SM_KL + go, g_KL + base + go);
                CPA(sb + SM_VH + go, g_VH + base + go);
                CPA(sb + SM_VL + go, g_VL + base + go);
            }
            CPC(); CPW();
        }
        __syncthreads();

        // ---- QK^T: S = Qh*Kh + Ql*Kh + Qh*Kl
        float s[8][4];
        #pragma unroll
        for (int nt = 0; nt < 8; nt++)
            #pragma unroll
            for (int e = 0; e < 4; e++) s[nt][e] = 0.f;

        const int ntc = meta_only ? 2 : 8;
        #pragma unroll
        for (int ks = 0; ks < 8; ks++) {
            const int d0 = ks * 16;
            const int ar = m0 + (lane & 7) + (lane & 8);
            const int ac = d0 + ((lane & 16) >> 1);
            uint32_t ah[4], al[4];
            ldsm4(sb + SM_QH + swoff(ar, ac), ah);
            ldsm4(sb + SM_QL + swoff(ar, ac), al);
            for (int nt = 0; nt < ntc; nt++) {
                const int br = nt * 8 + (lane & 7);
                const int bc = d0 + (lane & 8);
                uint32_t bh[2], bl[2];
                ldsm2(sb + SM_KH + swoff(br, bc), bh);
                ldsm2(sb + SM_KL + swoff(br, bc), bl);
                mma16816(s[nt], ah, bh);
                mma16816(s[nt], al, bh);
                mma16816(s[nt], ah, bl);
            }
        }

        // ---- mask + static-max softmax: p = exp(s*scale)
        {
            const int i_r0 = i0 + m0 + r, i_r1 = i_r0 + 8;
            float rs0 = 0.f, rs1 = 0.f;
            for (int nt = 0; nt < ntc; nt++) {
                const int jb = j0 + nt * 8 + c2;
                bool ok0 = (i_r0 >= jb)     && (((i_r0 - jb)     <= WINDOW) || (jb     < NMETA));
                bool ok1 = (i_r0 >= jb + 1) && (((i_r0 - jb - 1) <= WINDOW) || (jb + 1 < NMETA));
                bool ok2 = (i_r1 >= jb)     && (((i_r1 - jb)     <= WINDOW) || (jb     < NMETA));
                bool ok3 = (i_r1 >= jb + 1) && (((i_r1 - jb - 1) <= WINDOW) || (jb + 1 < NMETA));
                float p0 = ok0 ? __expf(s[nt][0] * SCALE) : 0.f;
                float p1 = ok1 ? __expf(s[nt][1] * SCALE) : 0.f;
                float p2 = ok2 ? __expf(s[nt][2] * SCALE) : 0.f;
                float p3 = ok3 ? __expf(s[nt][3] * SCALE) : 0.f;
                s[nt][0] = p0; s[nt][1] = p1; s[nt][2] = p2; s[nt][3] = p3;
                rs0 += p0 + p1; rs1 += p2 + p3;
            }
            rs0 += __shfl_xor_sync(0xffffffffu, rs0, 1);
            rs0 += __shfl_xor_sync(0xffffffffu, rs0, 2);
            rs1 += __shfl_xor_sync(0xffffffffu, rs1, 1);
            rs1 += __shfl_xor_sync(0xffffffffu, rs1, 2);
            l0 += rs0; l1 += rs1;
        }

        // ---- PV: O += Ph*Vh + Pl*Vh + Ph*Vl  (P converted in registers)
        const int kc = meta_only ? 1 : 4;
        for (int kk = 0; kk < kc; kk++) {
            uint32_t pah[4], pal[4];
            split2(s[2 * kk][0],     s[2 * kk][1],     pah[0], pal[0]);
            split2(s[2 * kk][2],     s[2 * kk][3],     pah[1], pal[1]);
            split2(s[2 * kk + 1][0], s[2 * kk + 1][1], pah[2], pal[2]);
            split2(s[2 * kk + 1][2], s[2 * kk + 1][3], pah[3], pal[3]);
            const int vr = kk * 16 + (lane & 15);
            #pragma unroll
            for (int dt = 0; dt < 16; dt++) {
                uint32_t bh[2], bl[2];
                ldsm2t(sb + SM_VH + swoff(vr, dt * 8), bh);
                ldsm2t(sb + SM_VL + swoff(vr, dt * 8), bl);
                mma16816(o[dt], pah, bh);
                mma16816(o[dt], pal, bh);
                mma16816(o[dt], pah, bl);
            }
        }
    }

    // ---- epilogue: normalize, store
    const float inv0 = 1.0f / l0, inv1 = 1.0f / l1;
    float* ob = O + (size_t)(i0 + m0 + r) * QSTR + h * 128 + c2;
    #pragma unroll
    for (int dt = 0; dt < 16; dt++) {
        float2 s0, s1;
        s0.x = o[dt][0] * inv0; s0.y = o[dt][1] * inv0;
        s1.x = o[dt][2] * inv1; s1.y = o[dt][3] * inv1;
        *(float2*)(ob + dt * 8)            = s0;
        *(float2*)(ob + dt * 8 + 8 * QSTR) = s1;
    }
}

extern "C" void kernel_launch(void* const* d_in, const int* in_sizes, int n_in,
                              void* d_out, int out_size)
{
    const float* Q = (const float*)d_in[0];
    const float* K = (const float*)d_in[1];
    const float* V = (const float*)d_in[2];
    float* O = (float*)d_out;

    const int S = in_sizes[0] / QSTR;   // 2048

    prep_kv<<<(8 * 2048 * 64) / 256, 256>>>(K, V);

    cudaFuncSetAttribute(swa_mma_kernel,
                         cudaFuncAttributeMaxDynamicSharedMemorySize, SMEM_BYTES);

    dim3 grid(S / BM, 32);
    swa_mma_kernel<<<grid, NTH, SMEM_BYTES>>>(Q, O);
}

// round 11
// speedup vs baseline: 2.3251x; 1.1320x over previous
#include <cuda_runtime.h>
#include <cuda_bf16.h>
#include <cstdint>

#define WINDOW 512
#define NMETA  4
#define BM     64
#define BN     32
#define NTH    128
#define QSTR   4096
#define KSTR   1024
#define SCALE  0.08838834764831845f

// smem: Q hi/lo [64][256B] + two KV buffers (KH,KL,VH,VL each [32][256B])
#define SM_QH  0
#define SM_QL  16384
#define SM_BUF 32768
#define BUF_SZ 32768
#define KOFF_L 8192
#define VOFF_H 16384
#define VOFF_L 24576
#define SMEM_BYTES 98304

// pre-converted K/V scratch: [8 kv-heads][2048 rows][256 B], smem-identical layout
__device__ __align__(16) char g_KH[8 * 2048 * 256];
__device__ __align__(16) char g_KL[8 * 2048 * 256];
__device__ __align__(16) char g_VH[8 * 2048 * 256];
__device__ __align__(16) char g_VL[8 * 2048 * 256];

__device__ __forceinline__ uint32_t s2u(const void* p){
    uint32_t a;
    asm("{ .reg .u64 t; cvta.to.shared.u64 t, %1; cvt.u32.u64 %0, t; }":"=r"(a):"l"(p));
    return a;
}
__device__ __forceinline__ uint32_t swoff(int row, int col){
    return (uint32_t)(row * 256 + (((col >> 3) ^ (row & 7)) << 4));
}
__device__ __forceinline__ void split2(float a, float b, uint32_t& hp, uint32_t& lp){
    __nv_bfloat16 ah = __float2bfloat16(a), bh = __float2bfloat16(b);
    __nv_bfloat16 al = __float2bfloat16(a - __bfloat162float(ah));
    __nv_bfloat16 bl = __float2bfloat16(b - __bfloat162float(bh));
    hp = (uint32_t)__bfloat16_as_ushort(ah) | ((uint32_t)__bfloat16_as_ushort(bh) << 16);
    lp = (uint32_t)__bfloat16_as_ushort(al) | ((uint32_t)__bfloat16_as_ushort(bl) << 16);
}
__device__ __forceinline__ void ldsm4(uint32_t a, uint32_t r[4]){
    asm volatile("ldmatrix.sync.aligned.m8n8.x4.shared.b16 {%0,%1,%2,%3},[%4];"
        : "=r"(r[0]), "=r"(r[1]), "=r"(r[2]), "=r"(r[3]) : "r"(a));
}
__device__ __forceinline__ void ldsm2(uint32_t a, uint32_t r[2]){
    asm volatile("ldmatrix.sync.aligned.m8n8.x2.shared.b16 {%0,%1},[%2];"
        : "=r"(r[0]), "=r"(r[1]) : "r"(a));
}
__device__ __forceinline__ void ldsm2t(uint32_t a, uint32_t r[2]){
    asm volatile("ldmatrix.sync.aligned.m8n8.x2.trans.shared.b16 {%0,%1},[%2];"
        : "=r"(r[0]), "=r"(r[1]) : "r"(a));
}
__device__ __forceinline__ void mma16816(float d[4], const uint32_t a[4], const uint32_t b[2]){
    asm volatile("mma.sync.aligned.m16n8k16.row.col.f32.bf16.bf16.f32 "
        "{%0,%1,%2,%3},{%4,%5,%6,%7},{%8,%9},{%0,%1,%2,%3};"
        : "+f"(d[0]), "+f"(d[1]), "+f"(d[2]), "+f"(d[3])
        : "r"(a[0]), "r"(a[1]), "r"(a[2]), "r"(a[3]), "r"(b[0]), "r"(b[1]));
}
#define CPA(dst, src) asm volatile("cp.async.cg.shared.global [%0],[%1],16;"::"r"(dst),"l"(src):"memory")
#define CPC()  asm volatile("cp.async.commit_group;":::"memory")
#define CPW0() asm volatile("cp.async.wait_group 0;":::"memory")
#define CPW1() asm volatile("cp.async.wait_group 1;":::"memory")

// ---- prepass: K/V fp32 -> bf16 hi/lo scratch in swizzled layout
__global__ __launch_bounds__(256)
void prep_kv(const float* __restrict__ K, const float* __restrict__ V)
{
    int idx = blockIdx.x * 256 + threadIdx.x;
    int c2 = idx & 63;
    int n  = (idx >> 6) & 2047;
    int kh = idx >> 17;
    int c  = c2 * 2;
    const float2 k2 = *(const float2*)(K + (size_t)n * KSTR + kh * 128 + c);
    const float2 v2 = *(const float2*)(V + (size_t)n * KSTR + kh * 128 + c);
    size_t off = ((size_t)kh * 2048 + n) * 256
               + (uint32_t)((((c >> 3) ^ (n & 7)) << 4) + (c & 7) * 2);
    uint32_t hp, lp;
    split2(k2.x, k2.y, hp, lp);
    *(uint32_t*)(g_KH + off) = hp; *(uint32_t*)(g_KL + off) = lp;
    split2(v2.x, v2.y, hp, lp);
    *(uint32_t*)(g_VH + off) = hp; *(uint32_t*)(g_VL + off) = lp;
}

__global__ __launch_bounds__(NTH, 2)
void swa_mma_kernel(const float* __restrict__ Q, float* __restrict__ O)
{
    extern __shared__ char smp[];
    const uint32_t sb = s2u(smp);

    const int tid = threadIdx.x, wid = tid >> 5, lane = tid & 31;
    const int h = blockIdx.y, kh = h >> 2;
    const int i0 = ((int)gridDim.x - 1 - (int)blockIdx.x) * BM;  // heavy blocks first

    const int m0 = wid * 16;
    const int r  = lane >> 2;
    const int c2 = (lane & 3) * 2;

    const int t_lo = (i0 > WINDOW) ? ((i0 - WINDOW) >> 5) : 0;
    const int t_hi = (i0 + BM - 1) >> 5;
    const int ntiles = (t_lo == 0) ? (t_hi + 1) : (t_hi - t_lo + 2);

    // issue a tile's staging (cp.async) into buffer (tx&1), then commit
    auto stage = [&](int tx){
        const int t  = (t_lo == 0) ? tx : ((tx == 0) ? 0 : (t_lo + tx - 1));
        const int j0 = t << 5;
        const bool meta = (t == 0) && (t_lo >= 1);
        const size_t base = ((size_t)kh * 2048 + j0) * 256;
        const uint32_t db = sb + SM_BUF + (uint32_t)(tx & 1) * BUF_SZ;
        const int ng = meta ? 256 : 512;          // 16 rows vs 32 rows per array
        for (int g = tid; g < ng; g += NTH) {
            uint32_t go = (uint32_t)g * 16;
            CPA(db + go,          g_KH + base + go);
            CPA(db + KOFF_L + go, g_KL + base + go);
            CPA(db + VOFF_H + go, g_VH + base + go);
            CPA(db + VOFF_L + go, g_VL + base + go);
        }
        CPC();
    };

    stage(0);   // prefetch tile 0 first; overlaps with Q staging below

    // ---- stage Q -> bf16 hi/lo (swizzled [m][d])
    {
        const float4* Q4 = (const float4*)(Q + (size_t)i0 * QSTR + h * 128);
        #pragma unroll
        for (int it = 0; it < 16; it++) {
            int e = tid + it * NTH, m = e >> 5, c4 = e & 31, d = c4 * 4;
            float4 q = Q4[(size_t)m * (QSTR / 4) + c4];
            uint32_t h01, l01, h23, l23;
            split2(q.x, q.y, h01, l01); split2(q.z, q.w, h23, l23);
            uint32_t off = swoff(m, d) + (uint32_t)((d & 7) * 2);
            *(uint2*)(smp + SM_QH + off) = make_uint2(h01, h23);
            *(uint2*)(smp + SM_QL + off) = make_uint2(l01, l23);
        }
    }
    __syncthreads();

    // ---- hoist Q fragments into registers (once)
    uint32_t qh[8][4], ql[8][4];
    {
        const int ar = m0 + (lane & 7) + (lane & 8);
        #pragma unroll
        for (int ks = 0; ks < 8; ks++) {
            const int ac = ks * 16 + ((lane & 16) >> 1);
            ldsm4(sb + SM_QH + swoff(ar, ac), qh[ks]);
            ldsm4(sb + SM_QL + swoff(ar, ac), ql[ks]);
        }
    }

    float l0 = 0.f, l1 = 0.f;
    float o[16][4];
    #pragma unroll
    for (int dt = 0; dt < 16; dt++)
        #pragma unroll
        for (int e = 0; e < 4; e++) o[dt][e] = 0.f;

    for (int tix = 0; tix < ntiles; tix++) {
        const int t  = (t_lo == 0) ? tix : ((tix == 0) ? 0 : (t_lo + tix - 1));
        const int j0 = t << 5;
        const bool meta = (t == 0) && (t_lo >= 1);

        if (tix + 1 < ntiles) { stage(tix + 1); CPW1(); }
        else                  { CPW0(); }
        __syncthreads();

        const uint32_t db = sb + SM_BUF + (uint32_t)(tix & 1) * BUF_SZ;
        const int ntc = meta ? 1 : 4;
        const int dcl = i0 + m0 + 15 - j0;                  // causal reach for this warp
        const int ntmax = min(ntc, max(0, (dcl >> 3) + 1));
        const int kc    = meta ? 1 : 2;
        const int kkmax = min(kc,  max(0, (dcl >> 4) + 1));

        // ---- QK^T: S = Qh*Kh + Ql*Kh + Qh*Kl
        float s[4][4];
        #pragma unroll
        for (int nt = 0; nt < 4; nt++)
            #pragma unroll
            for (int e = 0; e < 4; e++) s[nt][e] = 0.f;

        #pragma unroll
        for (int ks = 0; ks < 8; ks++) {
            const int bc = ks * 16 + (lane & 8);
            for (int nt = 0; nt < ntmax; nt++) {
                const int br = nt * 8 + (lane & 7);
                uint32_t bh[2], bl[2];
                ldsm2(db + swoff(br, bc), bh);
                ldsm2(db + KOFF_L + swoff(br, bc), bl);
                mma16816(s[nt], qh[ks], bh);
                mma16816(s[nt], ql[ks], bh);
                mma16816(s[nt], qh[ks], bl);
            }
        }

        // ---- mask + static-max softmax: p = exp(s*scale)
        {
            const int i_r0 = i0 + m0 + r, i_r1 = i_r0 + 8;
            float rs0 = 0.f, rs1 = 0.f;
            for (int nt = 0; nt < ntc; nt++) {
                const int jb = j0 + nt * 8 + c2;
                bool ok0 = (i_r0 >= jb)     && (((i_r0 - jb)     <= WINDOW) || (jb     < NMETA));
                bool ok1 = (i_r0 >= jb + 1) && (((i_r0 - jb - 1) <= WINDOW) || (jb + 1 < NMETA));
                bool ok2 = (i_r1 >= jb)     && (((i_r1 - jb)     <= WINDOW) || (jb     < NMETA));
                bool ok3 = (i_r1 >= jb + 1) && (((i_r1 - jb - 1) <= WINDOW) || (jb + 1 < NMETA));
                float p0 = ok0 ? __expf(s[nt][0] * SCALE) : 0.f;
                float p1 = ok1 ? __expf(s[nt][1] * SCALE) : 0.f;
                float p2 = ok2 ? __expf(s[nt][2] * SCALE) : 0.f;
                float p3 = ok3 ? __expf(s[nt][3] * SCALE) : 0.f;
                s[nt][0] = p0; s[nt][1] = p1; s[nt][2] = p2; s[nt][3] = p3;
                rs0 += p0 + p1; rs1 += p2 + p3;
            }
            rs0 += __shfl_xor_sync(0xffffffffu, rs0, 1);
            rs0 += __shfl_xor_sync(0xffffffffu, rs0, 2);
            rs1 += __shfl_xor_sync(0xffffffffu, rs1, 1);
            rs1 += __shfl_xor_sync(0xffffffffu, rs1, 2);
            l0 += rs0; l1 += rs1;
        }

        // ---- PV: O += Ph*Vh + Pl*Vh + Ph*Vl  (P converted in registers)
        for (int kk = 0; kk < kkmax; kk++) {
            uint32_t pah[4], pal[4];
            split2(s[2 * kk][0],     s[2 * kk][1],     pah[0], pal[0]);
            split2(s[2 * kk][2],     s[2 * kk][3],     pah[1], pal[1]);
            split2(s[2 * kk + 1][0], s[2 * kk + 1][1], pah[2], pal[2]);
            split2(s[2 * kk + 1][2], s[2 * kk + 1][3], pah[3], pal[3]);
            const int vr = kk * 16 + (lane & 15);
            #pragma unroll
            for (int dt = 0; dt < 16; dt++) {
                uint32_t bh[2], bl[2];
                ldsm2t(db + VOFF_H + swoff(vr, dt * 8), bh);
                ldsm2t(db + VOFF_L + swoff(vr, dt * 8), bl);
                mma16816(o[dt], pah, bh);
                mma16816(o[dt], pal, bh);
                mma16816(o[dt], pah, bl);
            }
        }
        __syncthreads();   // all reads of buf[tix&1] done before tile tix+2 overwrites it
    }

    // ---- epilogue: normalize, store
    const float inv0 = 1.0f / l0, inv1 = 1.0f / l1;
    float* ob = O + (size_t)(i0 + m0 + r) * QSTR + h * 128 + c2;
    #pragma unroll
    for (int dt = 0; dt < 16; dt++) {
        float2 s0, s1;
        s0.x = o[dt][0] * inv0; s0.y = o[dt][1] * inv0;
        s1.x = o[dt][2] * inv1; s1.y = o[dt][3] * inv1;
        *(float2*)(ob + dt * 8)            = s0;
        *(float2*)(ob + dt * 8 + 8 * QSTR) = s1;
    }
}

extern "C" void kernel_launch(void* const* d_in, const int* in_sizes, int n_in,
                              void* d_out, int out_size)
{
    const float* Q = (const float*)d_in[0];
    const float* K = (const float*)d_in[1];
    const float* V = (const float*)d_in[2];
    float* O = (float*)d_out;

    const int S = in_sizes[0] / QSTR;   // 2048

    prep_kv<<<(8 * 2048 * 64) / 256, 256>>>(K, V);

    cudaFuncSetAttribute(swa_mma_kernel,
                         cudaFuncAttributeMaxDynamicSharedMemorySize, SMEM_BYTES);

    dim3 grid(S / BM, 32);
    swa_mma_kernel<<<grid, NTH, SMEM_BYTES>>>(Q, O);
}